// round 10
// baseline (speedup 1.0000x reference)
#include <cuda_runtime.h>
#include <cuda_fp16.h>

#define BB 128  // batch
#define BU 32   // batch in uint2 units (4 halves each)

// ---------------- padded geometry, fp16 (halos stay zero: never written) ---
__device__ __align__(16) __half g_bin[9 * 34 * 34 * BB];
__device__ __align__(16) __half g_h1[32 * 18 * 18 * BB];
__device__ __align__(16) __half g_h2[128 * 10 * 10 * BB];
__device__ __align__(16) __half g_h3[512 * 6 * 6 * BB];
__device__ __align__(16) __half g_h4[4096 * BB];
__device__ __align__(16) __half g_g1[40960 * BB];
__device__ __align__(16) __half g_g2[20480 * BB];
__device__ __align__(16) __half2 g_mixh[83552 * 4];
__device__ __align__(16) float g_part[160 * BB];

__constant__ float GC[64] = {
    0, 0, 0, 0,   0, 0, 0, 1,   0, 1, 0, -1,  0, 1, 0, 0,
    0, 0, 1, -1,  0, 0, 1, 0,   0, 1, 1, -2,  0, 1, 1, -1,
    1, -1, -1, 1, 1, -1, -1, 2, 1, 0, -1, 0,  1, 0, -1, 1,
    1, -1, 0, 0,  1, -1, 0, 1,  1, 0, 0, -1,  1, 0, 0, 0};

#define OFF_C1 0
#define OFF_C2 224
#define OFF_C3 1120
#define OFF_C4 4704
#define OFF_L1 11872
#define OFF_L2 52832
#define OFF_L3 73312
#define N_NODES 83552

// ---------------- helpers ----------------
__device__ __forceinline__ __half2 u2h(unsigned int u) {
    __half2 h;
    *reinterpret_cast<unsigned int*>(&h) = u;
    return h;
}
__device__ __forceinline__ unsigned int h2u(__half2 h) {
    return *reinterpret_cast<unsigned int*>(&h);
}
// Horner: (w0 + w1*a) + b*(w2 + w3*a)
__device__ __forceinline__ __half2 gateh(__half2 a, __half2 b,
                                         __half2 w0, __half2 w1, __half2 w2, __half2 w3) {
    __half2 u = __hfma2(a, w1, w0);
    __half2 t = __hfma2(a, w3, w2);
    return __hfma2(b, t, u);
}

// ---------------- kernel 1: gate mixing -> duplicated half2 coefs ----------
__global__ void mix_kernel(const float* __restrict__ s0, const float* __restrict__ s1,
                           const float* __restrict__ s2, const float* __restrict__ s3,
                           const float* __restrict__ s4, const float* __restrict__ s5,
                           const float* __restrict__ s6, __half2* __restrict__ dst) {
    int tid = blockIdx.x * blockDim.x + threadIdx.x;
    if (tid >= N_NODES) return;
    const int offs[8] = {OFF_C1, OFF_C2, OFF_C3, OFF_C4, OFF_L1, OFF_L2, OFF_L3, N_NODES};
    const float* srcs[7] = {s0, s1, s2, s3, s4, s5, s6};
    int seg = 0;
    while (tid >= offs[seg + 1]) seg++;
    const float* w = srcs[seg] + (size_t)(tid - offs[seg]) * 16;

    float e[16];
    float mx = w[0];
#pragma unroll
    for (int i = 1; i < 16; i++) mx = fmaxf(mx, w[i]);
    float s = 0.f;
#pragma unroll
    for (int i = 0; i < 16; i++) { e[i] = __expf(w[i] - mx); s += e[i]; }
    float inv = 1.f / s;
    float m0 = 0.f, m1 = 0.f, m2 = 0.f, m3 = 0.f;
#pragma unroll
    for (int i = 0; i < 16; i++) {
        float p = e[i] * inv;
        m0 = fmaf(p, GC[i * 4 + 0], m0);
        m1 = fmaf(p, GC[i * 4 + 1], m1);
        m2 = fmaf(p, GC[i * 4 + 2], m2);
        m3 = fmaf(p, GC[i * 4 + 3], m3);
    }
    dst[tid * 4 + 0] = __float2half2_rn(m0);
    dst[tid * 4 + 1] = __float2half2_rn(m1);
    dst[tid * 4 + 2] = __float2half2_rn(m2);
    dst[tid * 4 + 3] = __float2half2_rn(m3);
}

// ---------------- kernel 2: binarize + BCHW -> CHWB fp16 (padded out) ------
__global__ void binarize_kernel(const float* __restrict__ x, __half* __restrict__ bin) {
    __shared__ float tile[32][33];
    int c = blockIdx.z;
    int h = blockIdx.y;
    int bc = blockIdx.x;
    int b = bc * 32 + threadIdx.y;
    tile[threadIdx.y][threadIdx.x] = x[(((size_t)b * 3 + c) * 32 + h) * 32 + threadIdx.x];
    __syncthreads();
    int w = threadIdx.y;
    int bout = bc * 32 + threadIdx.x;
    float v = tile[threadIdx.x][w];
    const float thr[3] = {0.25f, 0.5f, 0.75f};
    const __half one = __float2half(1.f), zero = __float2half(0.f);
#pragma unroll
    for (int t = 0; t < 3; t++) {
        size_t idx = (((size_t)(t * 3 + c)) * 34 * 34 + (size_t)(h + 1) * 34 + (w + 1)) * BB + bout;
        bin[idx] = (v > thr[t]) ? one : zero;
    }
}

// ---------------- c1: gather tree_conv (R9 style) ---------------------------
template <int Hin, int SPB, bool PADOUT>
__global__ void __launch_bounds__(32 * SPB, 4) tree_conv_kernel(
    const uint2* __restrict__ in, uint2* __restrict__ out,
    const int* __restrict__ leaf, const __half2* __restrict__ mixh) {
    constexpr int Win = Hin + 2;
    constexpr int Wo = Hin / 2;
    constexpr int Wop = PADOUT ? (Wo + 2) : Wo;
    int o = blockIdx.y;
    __shared__ __half2 smw[28];
    __shared__ int soff[8];
    int t = threadIdx.y * 32 + threadIdx.x;
    if (t < 28) smw[t] = mixh[o * 28 + t];
    if (t < 8) {
        int idx = leaf[o * 8 + t];
        int ch = idx / 9, p = idx % 9;
        soff[t] = (ch * Win * Win + (p / 3) * Win + (p % 3)) * BU;
    }
    __syncthreads();
    int s = blockIdx.x * SPB + threadIdx.y;
    int wo = s % Wo, ho = s / Wo;
    int lane = threadIdx.x;

    __half2 rlo = __float2half2_rn(-60000.f);
    __half2 rhi = rlo;
#pragma unroll
    for (int ph = 0; ph < 2; ph++) {
#pragma unroll
        for (int pw = 0; pw < 2; pw++) {
            int pos = ((2 * ho + ph) * Win + (2 * wo + pw)) * BU + lane;
            uint2 v[8];
#pragma unroll
            for (int l = 0; l < 8; l++) v[l] = in[soff[l] + pos];
            __half2 t0 = gateh(u2h(v[0].x), u2h(v[1].x), smw[0], smw[1], smw[2], smw[3]);
            __half2 t1 = gateh(u2h(v[2].x), u2h(v[3].x), smw[4], smw[5], smw[6], smw[7]);
            __half2 t2 = gateh(u2h(v[4].x), u2h(v[5].x), smw[8], smw[9], smw[10], smw[11]);
            __half2 t3 = gateh(u2h(v[6].x), u2h(v[7].x), smw[12], smw[13], smw[14], smw[15]);
            __half2 u0 = gateh(t0, t1, smw[16], smw[17], smw[18], smw[19]);
            __half2 u1 = gateh(t2, t3, smw[20], smw[21], smw[22], smw[23]);
            rlo = __hmax2(rlo, gateh(u0, u1, smw[24], smw[25], smw[26], smw[27]));
            t0 = gateh(u2h(v[0].y), u2h(v[1].y), smw[0], smw[1], smw[2], smw[3]);
            t1 = gateh(u2h(v[2].y), u2h(v[3].y), smw[4], smw[5], smw[6], smw[7]);
            t2 = gateh(u2h(v[4].y), u2h(v[5].y), smw[8], smw[9], smw[10], smw[11]);
            t3 = gateh(u2h(v[6].y), u2h(v[7].y), smw[12], smw[13], smw[14], smw[15]);
            u0 = gateh(t0, t1, smw[16], smw[17], smw[18], smw[19]);
            u1 = gateh(t2, t3, smw[20], smw[21], smw[22], smw[23]);
            rhi = __hmax2(rhi, gateh(u0, u1, smw[24], smw[25], smw[26], smw[27]));
        }
    }
    size_t oidx;
    if (PADOUT)
        oidx = ((size_t)o * Wop * Wop + (size_t)(ho + 1) * Wop + (wo + 1)) * BU + lane;
    else
        oidx = ((size_t)o * Wo * Wo + (size_t)ho * Wo + wo) * BU + lane;
    out[oidx] = make_uint2(h2u(rlo), h2u(rhi));
}

// ---------------- c2/c3/c4: smem-staged tree_conv ---------------------------
// Block = (output channel o, batch chunk bq of BQ8 uint2). The 8 leaves of o
// touch <=2 distinct input channels (generator cpt=2); stage those 2 padded
// planes in smem, then all gathers are conflict-free LDS.
template <int Hin, int BQ8, int THREADS, bool PADOUT>
__global__ void __launch_bounds__(THREADS) tree_conv_smem_kernel(
    const uint2* __restrict__ in, uint2* __restrict__ out,
    const int* __restrict__ leaf, const __half2* __restrict__ mixh) {
    constexpr int Win = Hin + 2;
    constexpr int Wo = Hin / 2;
    constexpr int Wop = PADOUT ? (Wo + 2) : Wo;
    constexpr int PLANE = Win * Win;
    constexpr int OPW = 32 / BQ8;                    // ops per warp
    constexpr int ITEMS = Wo * Wo * BQ8;
    constexpr int NW = THREADS / 32;
    constexpr int OPS_PER_SWEEP = NW * OPW;
    constexpr int NSWEEP = ITEMS / THREADS;

    extern __shared__ uint2 sIn[];                   // [2][PLANE][BQ8]
    __shared__ __half2 smw[28];
    __shared__ int ssoff[8];
    __shared__ int schan[2];

    int tid = threadIdx.x;
    int o = blockIdx.y;
    int bq = blockIdx.x;
    if (tid < 28) smw[tid] = mixh[o * 28 + tid];
    if (tid == 0) {
        int ch[8], pos[8];
#pragma unroll
        for (int l = 0; l < 8; l++) {
            int idx = leaf[o * 8 + l];
            ch[l] = idx / 9;
            int p = idx % 9;
            pos[l] = (p / 3) * Win + (p % 3);
        }
        int cA = ch[0], cB = cA;
#pragma unroll
        for (int l = 1; l < 8; l++)
            if (ch[l] != cA && cB == cA) cB = ch[l];
        schan[0] = cA; schan[1] = cB;
#pragma unroll
        for (int l = 0; l < 8; l++)
            ssoff[l] = ((ch[l] == cA ? 0 : 1) * PLANE + pos[l]) * BQ8;
    }
    __syncthreads();

    // load the two channel planes (coalesced 128B rows)
    {
        const uint2* gA = in + (size_t)schan[0] * PLANE * BU + bq * BQ8;
        const uint2* gB = in + (size_t)schan[1] * PLANE * BU + bq * BQ8;
        for (int i = tid; i < PLANE * BQ8; i += THREADS) {
            int px = i / BQ8, j = i - px * BQ8;
            sIn[i] = gA[(size_t)px * BU + j];
            sIn[PLANE * BQ8 + i] = gB[(size_t)px * BU + j];
        }
    }
    __syncthreads();

    __half2 w[28];
#pragma unroll
    for (int k = 0; k < 28; k++) w[k] = smw[k];
    int soff[8];
#pragma unroll
    for (int l = 0; l < 8; l++) soff[l] = ssoff[l];

    int warp = tid / 32, lane = tid % 32;
    int gp = lane / BQ8;    // op slot within warp
    int j = lane % BQ8;     // batch uint2 slot

#pragma unroll
    for (int sweep = 0; sweep < NSWEEP; sweep++) {
        int op = sweep * OPS_PER_SWEEP + warp * OPW + gp;
        int ho = op / Wo, wo = op % Wo;
        __half2 rlo = __float2half2_rn(-60000.f), rhi = rlo;
#pragma unroll
        for (int ph = 0; ph < 2; ph++) {
#pragma unroll
            for (int pw = 0; pw < 2; pw++) {
                int base = ((2 * ho + ph) * Win + 2 * wo + pw) * BQ8 + j;
                uint2 v[8];
#pragma unroll
                for (int l = 0; l < 8; l++) v[l] = sIn[soff[l] + base];
                __half2 t0 = gateh(u2h(v[0].x), u2h(v[1].x), w[0], w[1], w[2], w[3]);
                __half2 t1 = gateh(u2h(v[2].x), u2h(v[3].x), w[4], w[5], w[6], w[7]);
                __half2 t2 = gateh(u2h(v[4].x), u2h(v[5].x), w[8], w[9], w[10], w[11]);
                __half2 t3 = gateh(u2h(v[6].x), u2h(v[7].x), w[12], w[13], w[14], w[15]);
                __half2 u0 = gateh(t0, t1, w[16], w[17], w[18], w[19]);
                __half2 u1 = gateh(t2, t3, w[20], w[21], w[22], w[23]);
                rlo = __hmax2(rlo, gateh(u0, u1, w[24], w[25], w[26], w[27]));
                t0 = gateh(u2h(v[0].y), u2h(v[1].y), w[0], w[1], w[2], w[3]);
                t1 = gateh(u2h(v[2].y), u2h(v[3].y), w[4], w[5], w[6], w[7]);
                t2 = gateh(u2h(v[4].y), u2h(v[5].y), w[8], w[9], w[10], w[11]);
                t3 = gateh(u2h(v[6].y), u2h(v[7].y), w[12], w[13], w[14], w[15]);
                u0 = gateh(t0, t1, w[16], w[17], w[18], w[19]);
                u1 = gateh(t2, t3, w[20], w[21], w[22], w[23]);
                rhi = __hmax2(rhi, gateh(u0, u1, w[24], w[25], w[26], w[27]));
            }
        }
        size_t oidx;
        if (PADOUT)
            oidx = ((size_t)o * Wop * Wop + (size_t)(ho + 1) * Wop + (wo + 1)) * BU + bq * BQ8 + j;
        else
            oidx = ((size_t)o * Wo * Wo + op) * BU + bq * BQ8 + j;
        out[oidx] = make_uint2(h2u(rlo), h2u(rhi));
    }
}

// ---------------- logic layers: fp16, uint2 lanes ----------------
__global__ void logic_kernel(const uint2* __restrict__ in, uint2* __restrict__ out,
                             const int* __restrict__ ai, const int* __restrict__ bi,
                             const __half2* __restrict__ mixh, int Dout) {
    int tid = blockIdx.x * blockDim.x + threadIdx.x;
    if (tid >= Dout * BU) return;
    int j = tid >> 5, lane = tid & 31;
    __half2 w0 = mixh[j * 4 + 0], w1 = mixh[j * 4 + 1];
    __half2 w2 = mixh[j * 4 + 2], w3 = mixh[j * 4 + 3];
    uint2 a = in[(size_t)__ldg(&ai[j]) * BU + lane];
    uint2 b = in[(size_t)__ldg(&bi[j]) * BU + lane];
    __half2 rlo = gateh(u2h(a.x), u2h(b.x), w0, w1, w2, w3);
    __half2 rhi = gateh(u2h(a.y), u2h(b.y), w0, w1, w2, w3);
    out[tid] = make_uint2(h2u(rlo), h2u(rhi));
}

// ---------------- logic3 fused with group-sum partials (float accum) -------
__global__ void __launch_bounds__(128) logic3_sum_kernel(
    const uint2* __restrict__ in, float4* __restrict__ part,
    const int* __restrict__ ai, const int* __restrict__ bi,
    const __half2* __restrict__ mixh) {
    __shared__ float4 red[4][32];
    int blk = blockIdx.x;
    int wz = threadIdx.y;
    int lane = threadIdx.x;
    int j0 = blk * 64 + wz * 16;
    float4 acc = make_float4(0.f, 0.f, 0.f, 0.f);
#pragma unroll
    for (int jj = 0; jj < 16; jj++) {
        int j = j0 + jj;
        __half2 w0 = mixh[j * 4 + 0], w1 = mixh[j * 4 + 1];
        __half2 w2 = mixh[j * 4 + 2], w3 = mixh[j * 4 + 3];
        uint2 a = in[(size_t)__ldg(&ai[j]) * BU + lane];
        uint2 b = in[(size_t)__ldg(&bi[j]) * BU + lane];
        float2 glo = __half22float2(gateh(u2h(a.x), u2h(b.x), w0, w1, w2, w3));
        float2 ghi = __half22float2(gateh(u2h(a.y), u2h(b.y), w0, w1, w2, w3));
        acc.x += glo.x; acc.y += glo.y; acc.z += ghi.x; acc.w += ghi.y;
    }
    red[wz][lane] = acc;
    __syncthreads();
    if (wz == 0) {
        float4 s = red[0][lane], s1 = red[1][lane], s2 = red[2][lane], s3 = red[3][lane];
        s.x += s1.x + s2.x + s3.x;
        s.y += s1.y + s2.y + s3.y;
        s.z += s1.z + s2.z + s3.z;
        s.w += s1.w + s2.w + s3.w;
        part[(size_t)blk * BU + lane] = s;
    }
}

// ---------------- final reduce ----------------
__global__ void final_sum_kernel(const float* __restrict__ part, float* __restrict__ out) {
    int tid = blockIdx.x * blockDim.x + threadIdx.x;
    if (tid >= 1280) return;
    int cls = tid >> 7, b = tid & 127;
    float s = 0.f;
#pragma unroll
    for (int k = 0; k < 16; k++) s += part[(size_t)(cls * 16 + k) * BB + b];
    out[b * 10 + cls] = s * 0.01f;
}

// ---------------- host launcher ----------------
extern "C" void kernel_launch(void* const* d_in, const int* in_sizes, int n_in,
                              void* d_out, int out_size) {
    const float* x   = (const float*)d_in[0];
    const int*   c1i = (const int*)d_in[1];  const float* c1w = (const float*)d_in[2];
    const int*   c2i = (const int*)d_in[3];  const float* c2w = (const float*)d_in[4];
    const int*   c3i = (const int*)d_in[5];  const float* c3w = (const float*)d_in[6];
    const int*   c4i = (const int*)d_in[7];  const float* c4w = (const float*)d_in[8];
    const int*   l1a = (const int*)d_in[9];  const int* l1b = (const int*)d_in[10];
    const float* l1w = (const float*)d_in[11];
    const int*   l2a = (const int*)d_in[12]; const int* l2b = (const int*)d_in[13];
    const float* l2w = (const float*)d_in[14];
    const int*   l3a = (const int*)d_in[15]; const int* l3b = (const int*)d_in[16];
    const float* l3w = (const float*)d_in[17];

    __half *bin, *h1, *h2, *h3, *h4, *g1, *g2;
    __half2* mixh;
    float* part;
    cudaGetSymbolAddress((void**)&bin,  g_bin);
    cudaGetSymbolAddress((void**)&h1,   g_h1);
    cudaGetSymbolAddress((void**)&h2,   g_h2);
    cudaGetSymbolAddress((void**)&h3,   g_h3);
    cudaGetSymbolAddress((void**)&h4,   g_h4);
    cudaGetSymbolAddress((void**)&g1,   g_g1);
    cudaGetSymbolAddress((void**)&g2,   g_g2);
    cudaGetSymbolAddress((void**)&mixh, g_mixh);
    cudaGetSymbolAddress((void**)&part, g_part);

    // dynamic smem sizes (bytes)
    const int SM_C2 = 2 * 18 * 18 * 16 * 8;   // 82944
    const int SM_C3 = 2 * 10 * 10 * 16 * 8;   // 25600
    const int SM_C4 = 2 * 6 * 6 * 32 * 8;     // 18432
    cudaFuncSetAttribute((const void*)tree_conv_smem_kernel<16, 16, 256, true>,
                         cudaFuncAttributeMaxDynamicSharedMemorySize, SM_C2);

    mix_kernel<<<(N_NODES + 127) / 128, 128>>>(c1w, c2w, c3w, c4w, l1w, l2w, l3w, mixh);
    binarize_kernel<<<dim3(4, 32, 3), dim3(32, 32)>>>(x, bin);

    // c1: gather kernel (input planes too big to stage)
    tree_conv_kernel<32, 8, true><<<dim3(32, 32), dim3(32, 8)>>>(
        (const uint2*)bin, (uint2*)h1, c1i, mixh + OFF_C1 * 4);
    // c2/c3/c4: smem-staged, 2 input planes per output channel
    tree_conv_smem_kernel<16, 16, 256, true><<<dim3(2, 128), 256, SM_C2>>>(
        (const uint2*)h1, (uint2*)h2, c2i, mixh + OFF_C2 * 4);
    tree_conv_smem_kernel<8, 16, 256, true><<<dim3(2, 512), 256, SM_C3>>>(
        (const uint2*)h2, (uint2*)h3, c3i, mixh + OFF_C3 * 4);
    tree_conv_smem_kernel<4, 32, 128, false><<<dim3(1, 1024), 128, SM_C4>>>(
        (const uint2*)h3, (uint2*)h4, c4i, mixh + OFF_C4 * 4);

    logic_kernel<<<(40960 * BU) / 256, 256>>>((const uint2*)h4, (uint2*)g1, l1a, l1b, mixh + OFF_L1 * 4, 40960);
    logic_kernel<<<(20480 * BU) / 256, 256>>>((const uint2*)g1, (uint2*)g2, l2a, l2b, mixh + OFF_L2 * 4, 20480);
    logic3_sum_kernel<<<160, dim3(32, 4)>>>((const uint2*)g2, (float4*)part, l3a, l3b, mixh + OFF_L3 * 4);
    final_sum_kernel<<<10, 128>>>(part, (float*)d_out);
}

// round 11
// speedup vs baseline: 1.0419x; 1.0419x over previous
#include <cuda_runtime.h>
#include <cuda_fp16.h>

#define BB 128  // batch
#define BU 32   // batch in uint2 units (4 halves each)

// ---------------- padded geometry, fp16 (halos stay zero: never written) ---
__device__ __align__(16) __half g_bin[9 * 34 * 34 * BB];
__device__ __align__(16) __half g_h1[32 * 18 * 18 * BB];
__device__ __align__(16) __half g_h2[128 * 10 * 10 * BB];
__device__ __align__(16) __half g_h3[512 * 6 * 6 * BB];
__device__ __align__(16) __half g_h4[4096 * BB];
__device__ __align__(16) __half g_g1[40960 * BB];
__device__ __align__(16) __half g_g2[20480 * BB];
__device__ __align__(16) __half2 g_mixh[83552 * 4];
__device__ __align__(16) float g_part[160 * BB];

__constant__ float GC[64] = {
    0, 0, 0, 0,   0, 0, 0, 1,   0, 1, 0, -1,  0, 1, 0, 0,
    0, 0, 1, -1,  0, 0, 1, 0,   0, 1, 1, -2,  0, 1, 1, -1,
    1, -1, -1, 1, 1, -1, -1, 2, 1, 0, -1, 0,  1, 0, -1, 1,
    1, -1, 0, 0,  1, -1, 0, 1,  1, 0, 0, -1,  1, 0, 0, 0};

#define OFF_C1 0
#define OFF_C2 224
#define OFF_C3 1120
#define OFF_C4 4704
#define OFF_L1 11872
#define OFF_L2 52832
#define OFF_L3 73312
#define N_NODES 83552

// ---------------- helpers ----------------
__device__ __forceinline__ __half2 u2h(unsigned int u) {
    __half2 h;
    *reinterpret_cast<unsigned int*>(&h) = u;
    return h;
}
__device__ __forceinline__ unsigned int h2u(__half2 h) {
    return *reinterpret_cast<unsigned int*>(&h);
}
// Horner: (w0 + w1*a) + b*(w2 + w3*a)
__device__ __forceinline__ __half2 gateh(__half2 a, __half2 b,
                                         __half2 w0, __half2 w1, __half2 w2, __half2 w3) {
    __half2 u = __hfma2(a, w1, w0);
    __half2 t = __hfma2(a, w3, w2);
    return __hfma2(b, t, u);
}

// ---------------- kernel 1: gate mixing -> duplicated half2 coefs ----------
__global__ void mix_kernel(const float* __restrict__ s0, const float* __restrict__ s1,
                           const float* __restrict__ s2, const float* __restrict__ s3,
                           const float* __restrict__ s4, const float* __restrict__ s5,
                           const float* __restrict__ s6, __half2* __restrict__ dst) {
    int tid = blockIdx.x * blockDim.x + threadIdx.x;
    if (tid >= N_NODES) return;
    const int offs[8] = {OFF_C1, OFF_C2, OFF_C3, OFF_C4, OFF_L1, OFF_L2, OFF_L3, N_NODES};
    const float* srcs[7] = {s0, s1, s2, s3, s4, s5, s6};
    int seg = 0;
    while (tid >= offs[seg + 1]) seg++;
    const float* w = srcs[seg] + (size_t)(tid - offs[seg]) * 16;

    float e[16];
    float mx = w[0];
#pragma unroll
    for (int i = 1; i < 16; i++) mx = fmaxf(mx, w[i]);
    float s = 0.f;
#pragma unroll
    for (int i = 0; i < 16; i++) { e[i] = __expf(w[i] - mx); s += e[i]; }
    float inv = 1.f / s;
    float m0 = 0.f, m1 = 0.f, m2 = 0.f, m3 = 0.f;
#pragma unroll
    for (int i = 0; i < 16; i++) {
        float p = e[i] * inv;
        m0 = fmaf(p, GC[i * 4 + 0], m0);
        m1 = fmaf(p, GC[i * 4 + 1], m1);
        m2 = fmaf(p, GC[i * 4 + 2], m2);
        m3 = fmaf(p, GC[i * 4 + 3], m3);
    }
    dst[tid * 4 + 0] = __float2half2_rn(m0);
    dst[tid * 4 + 1] = __float2half2_rn(m1);
    dst[tid * 4 + 2] = __float2half2_rn(m2);
    dst[tid * 4 + 3] = __float2half2_rn(m3);
}

// ---------------- kernel 2: binarize + BCHW -> CHWB fp16 (padded out) ------
__global__ void binarize_kernel(const float* __restrict__ x, __half* __restrict__ bin) {
    __shared__ float tile[32][33];
    int c = blockIdx.z;
    int h = blockIdx.y;
    int bc = blockIdx.x;
    int b = bc * 32 + threadIdx.y;
    tile[threadIdx.y][threadIdx.x] = x[(((size_t)b * 3 + c) * 32 + h) * 32 + threadIdx.x];
    __syncthreads();
    int w = threadIdx.y;
    int bout = bc * 32 + threadIdx.x;
    float v = tile[threadIdx.x][w];
    const float thr[3] = {0.25f, 0.5f, 0.75f};
    const __half one = __float2half(1.f), zero = __float2half(0.f);
#pragma unroll
    for (int t = 0; t < 3; t++) {
        size_t idx = (((size_t)(t * 3 + c)) * 34 * 34 + (size_t)(h + 1) * 34 + (w + 1)) * BB + bout;
        bin[idx] = (v > thr[t]) ? one : zero;
    }
}

// ---------------- c1: gather tree_conv ---------------------------
template <int Hin, int SPB, bool PADOUT>
__global__ void __launch_bounds__(32 * SPB, 4) tree_conv_kernel(
    const uint2* __restrict__ in, uint2* __restrict__ out,
    const int* __restrict__ leaf, const __half2* __restrict__ mixh) {
    constexpr int Win = Hin + 2;
    constexpr int Wo = Hin / 2;
    constexpr int Wop = PADOUT ? (Wo + 2) : Wo;
    int o = blockIdx.y;
    __shared__ __half2 smw[28];
    __shared__ int soff[8];
    int t = threadIdx.y * 32 + threadIdx.x;
    if (t < 28) smw[t] = mixh[o * 28 + t];
    if (t < 8) {
        int idx = leaf[o * 8 + t];
        int ch = idx / 9, p = idx % 9;
        soff[t] = (ch * Win * Win + (p / 3) * Win + (p % 3)) * BU;
    }
    __syncthreads();
    int s = blockIdx.x * SPB + threadIdx.y;
    int wo = s % Wo, ho = s / Wo;
    int lane = threadIdx.x;

    __half2 rlo = __float2half2_rn(-60000.f);
    __half2 rhi = rlo;
#pragma unroll
    for (int ph = 0; ph < 2; ph++) {
#pragma unroll
        for (int pw = 0; pw < 2; pw++) {
            int pos = ((2 * ho + ph) * Win + (2 * wo + pw)) * BU + lane;
            uint2 v[8];
#pragma unroll
            for (int l = 0; l < 8; l++) v[l] = in[soff[l] + pos];
            __half2 t0 = gateh(u2h(v[0].x), u2h(v[1].x), smw[0], smw[1], smw[2], smw[3]);
            __half2 t1 = gateh(u2h(v[2].x), u2h(v[3].x), smw[4], smw[5], smw[6], smw[7]);
            __half2 t2 = gateh(u2h(v[4].x), u2h(v[5].x), smw[8], smw[9], smw[10], smw[11]);
            __half2 t3 = gateh(u2h(v[6].x), u2h(v[7].x), smw[12], smw[13], smw[14], smw[15]);
            __half2 u0 = gateh(t0, t1, smw[16], smw[17], smw[18], smw[19]);
            __half2 u1 = gateh(t2, t3, smw[20], smw[21], smw[22], smw[23]);
            rlo = __hmax2(rlo, gateh(u0, u1, smw[24], smw[25], smw[26], smw[27]));
            t0 = gateh(u2h(v[0].y), u2h(v[1].y), smw[0], smw[1], smw[2], smw[3]);
            t1 = gateh(u2h(v[2].y), u2h(v[3].y), smw[4], smw[5], smw[6], smw[7]);
            t2 = gateh(u2h(v[4].y), u2h(v[5].y), smw[8], smw[9], smw[10], smw[11]);
            t3 = gateh(u2h(v[6].y), u2h(v[7].y), smw[12], smw[13], smw[14], smw[15]);
            u0 = gateh(t0, t1, smw[16], smw[17], smw[18], smw[19]);
            u1 = gateh(t2, t3, smw[20], smw[21], smw[22], smw[23]);
            rhi = __hmax2(rhi, gateh(u0, u1, smw[24], smw[25], smw[26], smw[27]));
        }
    }
    size_t oidx;
    if (PADOUT)
        oidx = ((size_t)o * Wop * Wop + (size_t)(ho + 1) * Wop + (wo + 1)) * BU + lane;
    else
        oidx = ((size_t)o * Wo * Wo + (size_t)ho * Wo + wo) * BU + lane;
    out[oidx] = make_uint2(h2u(rlo), h2u(rhi));
}

// ---------------- c2/c3/c4: smem-staged tree_conv (2 input planes) ---------
template <int Hin, int BQ8, int THREADS, int MINB, bool PADOUT>
__global__ void __launch_bounds__(THREADS, MINB) tree_conv_smem_kernel(
    const uint2* __restrict__ in, uint2* __restrict__ out,
    const int* __restrict__ leaf, const __half2* __restrict__ mixh) {
    constexpr int Win = Hin + 2;
    constexpr int Wo = Hin / 2;
    constexpr int Wop = PADOUT ? (Wo + 2) : Wo;
    constexpr int PLANE = Win * Win;
    constexpr int OPW = 32 / BQ8;
    constexpr int ITEMS = Wo * Wo * BQ8;
    constexpr int NW = THREADS / 32;
    constexpr int OPS_PER_SWEEP = NW * OPW;
    constexpr int NSWEEP = ITEMS / THREADS;
    constexpr int ROW4 = BQ8 / 2;           // uint4 per pixel row chunk
    constexpr int CNT = PLANE * ROW4;       // uint4 per plane
    static_assert(ITEMS % THREADS == 0, "");

    extern __shared__ uint2 sIn[];          // [2][PLANE][BQ8]
    __shared__ __half2 smw[28];
    __shared__ int ssoff[8];
    __shared__ int schan[2];

    int tid = threadIdx.x;
    int o = blockIdx.y;
    int bq = blockIdx.x;
    if (tid < 28) smw[tid] = mixh[o * 28 + tid];
    if (tid == 0) {
        int ch[8], pos[8];
#pragma unroll
        for (int l = 0; l < 8; l++) {
            int idx = leaf[o * 8 + l];
            ch[l] = idx / 9;
            int p = idx % 9;
            pos[l] = (p / 3) * Win + (p % 3);
        }
        int cA = ch[0], cB = cA;
#pragma unroll
        for (int l = 1; l < 8; l++)
            if (ch[l] != cA && cB == cA) cB = ch[l];
        schan[0] = cA; schan[1] = cB;
#pragma unroll
        for (int l = 0; l < 8; l++)
            ssoff[l] = ((ch[l] == cA ? 0 : 1) * PLANE + pos[l]) * BQ8;
    }
    __syncthreads();

    // stage 2 planes with uint4 loads
    {
        int cA = schan[0], cB = schan[1];
        const uint4* g4 = (const uint4*)in;
        uint4* s4 = (uint4*)sIn;
        for (int i = tid; i < CNT; i += THREADS) {
            int px = i / ROW4, q = i - px * ROW4;
            size_t pbase = (size_t)px * (BU / 2) + bq * ROW4 + q;
            s4[i]       = g4[(size_t)cA * PLANE * (BU / 2) + pbase];
            s4[CNT + i] = g4[(size_t)cB * PLANE * (BU / 2) + pbase];
        }
    }
    __syncthreads();

    __half2 w[28];
#pragma unroll
    for (int k = 0; k < 28; k++) w[k] = smw[k];
    int soff[8];
#pragma unroll
    for (int l = 0; l < 8; l++) soff[l] = ssoff[l];

    int warp = tid / 32, lane = tid % 32;
    int gp = lane / BQ8;
    int j = lane % BQ8;

#pragma unroll
    for (int sweep = 0; sweep < NSWEEP; sweep++) {
        int op = sweep * OPS_PER_SWEEP + warp * OPW + gp;
        int ho = op / Wo, wo = op % Wo;
        __half2 rlo = __float2half2_rn(-60000.f), rhi = rlo;
#pragma unroll
        for (int ph = 0; ph < 2; ph++) {
#pragma unroll
            for (int pw = 0; pw < 2; pw++) {
                int base = ((2 * ho + ph) * Win + 2 * wo + pw) * BQ8 + j;
                uint2 v[8];
#pragma unroll
                for (int l = 0; l < 8; l++) v[l] = sIn[soff[l] + base];
                __half2 t0 = gateh(u2h(v[0].x), u2h(v[1].x), w[0], w[1], w[2], w[3]);
                __half2 t1 = gateh(u2h(v[2].x), u2h(v[3].x), w[4], w[5], w[6], w[7]);
                __half2 t2 = gateh(u2h(v[4].x), u2h(v[5].x), w[8], w[9], w[10], w[11]);
                __half2 t3 = gateh(u2h(v[6].x), u2h(v[7].x), w[12], w[13], w[14], w[15]);
                __half2 u0 = gateh(t0, t1, w[16], w[17], w[18], w[19]);
                __half2 u1 = gateh(t2, t3, w[20], w[21], w[22], w[23]);
                rlo = __hmax2(rlo, gateh(u0, u1, w[24], w[25], w[26], w[27]));
                t0 = gateh(u2h(v[0].y), u2h(v[1].y), w[0], w[1], w[2], w[3]);
                t1 = gateh(u2h(v[2].y), u2h(v[3].y), w[4], w[5], w[6], w[7]);
                t2 = gateh(u2h(v[4].y), u2h(v[5].y), w[8], w[9], w[10], w[11]);
                t3 = gateh(u2h(v[6].y), u2h(v[7].y), w[12], w[13], w[14], w[15]);
                u0 = gateh(t0, t1, w[16], w[17], w[18], w[19]);
                u1 = gateh(t2, t3, w[20], w[21], w[22], w[23]);
                rhi = __hmax2(rhi, gateh(u0, u1, w[24], w[25], w[26], w[27]));
            }
        }
        size_t oidx;
        if (PADOUT)
            oidx = ((size_t)o * Wop * Wop + (size_t)(ho + 1) * Wop + (wo + 1)) * BU + bq * BQ8 + j;
        else
            oidx = ((size_t)o * Wo * Wo + op) * BU + bq * BQ8 + j;
        out[oidx] = make_uint2(h2u(rlo), h2u(rhi));
    }
}

// ---------------- logic layers: fp16, uint4 lanes (8 halves) ---------------
__global__ void logic_kernel(const uint4* __restrict__ in, uint4* __restrict__ out,
                             const int* __restrict__ ai, const int* __restrict__ bi,
                             const uint4* __restrict__ mixh4, int Dout) {
    int tid = blockIdx.x * blockDim.x + threadIdx.x;
    if (tid >= Dout * 16) return;
    int j = tid >> 4, lane = tid & 15;
    uint4 wu = mixh4[j];
    __half2 w0 = u2h(wu.x), w1 = u2h(wu.y), w2 = u2h(wu.z), w3 = u2h(wu.w);
    uint4 a = in[(size_t)__ldg(&ai[j]) * 16 + lane];
    uint4 b = in[(size_t)__ldg(&bi[j]) * 16 + lane];
    uint4 r;
    r.x = h2u(gateh(u2h(a.x), u2h(b.x), w0, w1, w2, w3));
    r.y = h2u(gateh(u2h(a.y), u2h(b.y), w0, w1, w2, w3));
    r.z = h2u(gateh(u2h(a.z), u2h(b.z), w0, w1, w2, w3));
    r.w = h2u(gateh(u2h(a.w), u2h(b.w), w0, w1, w2, w3));
    out[tid] = r;
}

// ---------------- logic3 fused with group-sum partials (float accum) -------
__global__ void __launch_bounds__(128) logic3_sum_kernel(
    const uint2* __restrict__ in, float4* __restrict__ part,
    const int* __restrict__ ai, const int* __restrict__ bi,
    const __half2* __restrict__ mixh) {
    __shared__ float4 red[4][32];
    int blk = blockIdx.x;
    int wz = threadIdx.y;
    int lane = threadIdx.x;
    int j0 = blk * 64 + wz * 16;
    float4 acc = make_float4(0.f, 0.f, 0.f, 0.f);
#pragma unroll
    for (int jj = 0; jj < 16; jj++) {
        int j = j0 + jj;
        __half2 w0 = mixh[j * 4 + 0], w1 = mixh[j * 4 + 1];
        __half2 w2 = mixh[j * 4 + 2], w3 = mixh[j * 4 + 3];
        uint2 a = in[(size_t)__ldg(&ai[j]) * BU + lane];
        uint2 b = in[(size_t)__ldg(&bi[j]) * BU + lane];
        float2 glo = __half22float2(gateh(u2h(a.x), u2h(b.x), w0, w1, w2, w3));
        float2 ghi = __half22float2(gateh(u2h(a.y), u2h(b.y), w0, w1, w2, w3));
        acc.x += glo.x; acc.y += glo.y; acc.z += ghi.x; acc.w += ghi.y;
    }
    red[wz][lane] = acc;
    __syncthreads();
    if (wz == 0) {
        float4 s = red[0][lane], s1 = red[1][lane], s2 = red[2][lane], s3 = red[3][lane];
        s.x += s1.x + s2.x + s3.x;
        s.y += s1.y + s2.y + s3.y;
        s.z += s1.z + s2.z + s3.z;
        s.w += s1.w + s2.w + s3.w;
        part[(size_t)blk * BU + lane] = s;
    }
}

// ---------------- final reduce ----------------
__global__ void final_sum_kernel(const float* __restrict__ part, float* __restrict__ out) {
    int tid = blockIdx.x * blockDim.x + threadIdx.x;
    if (tid >= 1280) return;
    int cls = tid >> 7, b = tid & 127;
    float s = 0.f;
#pragma unroll
    for (int k = 0; k < 16; k++) s += part[(size_t)(cls * 16 + k) * BB + b];
    out[b * 10 + cls] = s * 0.01f;
}

// ---------------- host launcher ----------------
extern "C" void kernel_launch(void* const* d_in, const int* in_sizes, int n_in,
                              void* d_out, int out_size) {
    const float* x   = (const float*)d_in[0];
    const int*   c1i = (const int*)d_in[1];  const float* c1w = (const float*)d_in[2];
    const int*   c2i = (const int*)d_in[3];  const float* c2w = (const float*)d_in[4];
    const int*   c3i = (const int*)d_in[5];  const float* c3w = (const float*)d_in[6];
    const int*   c4i = (const int*)d_in[7];  const float* c4w = (const float*)d_in[8];
    const int*   l1a = (const int*)d_in[9];  const int* l1b = (const int*)d_in[10];
    const float* l1w = (const float*)d_in[11];
    const int*   l2a = (const int*)d_in[12]; const int* l2b = (const int*)d_in[13];
    const float* l2w = (const float*)d_in[14];
    const int*   l3a = (const int*)d_in[15]; const int* l3b = (const int*)d_in[16];
    const float* l3w = (const float*)d_in[17];

    __half *bin, *h1, *h2, *h3, *h4, *g1, *g2;
    __half2* mixh;
    float* part;
    cudaGetSymbolAddress((void**)&bin,  g_bin);
    cudaGetSymbolAddress((void**)&h1,   g_h1);
    cudaGetSymbolAddress((void**)&h2,   g_h2);
    cudaGetSymbolAddress((void**)&h3,   g_h3);
    cudaGetSymbolAddress((void**)&h4,   g_h4);
    cudaGetSymbolAddress((void**)&g1,   g_g1);
    cudaGetSymbolAddress((void**)&g2,   g_g2);
    cudaGetSymbolAddress((void**)&mixh, g_mixh);
    cudaGetSymbolAddress((void**)&part, g_part);

    // dynamic smem sizes (bytes) — all under the 48KB default limit
    const int SM_C2 = 2 * 18 * 18 * 8 * 8;    // 41472
    const int SM_C3 = 2 * 10 * 10 * 16 * 8;   // 25600
    const int SM_C4 = 2 * 6 * 6 * 32 * 8;     // 18432

    mix_kernel<<<(N_NODES + 127) / 128, 128>>>(c1w, c2w, c3w, c4w, l1w, l2w, l3w, mixh);
    binarize_kernel<<<dim3(4, 32, 3), dim3(32, 32)>>>(x, bin);

    // c1: gather kernel
    tree_conv_kernel<32, 8, true><<<dim3(32, 32), dim3(32, 8)>>>(
        (const uint2*)bin, (uint2*)h1, c1i, mixh + OFF_C1 * 4);
    // c2/c3/c4: smem-staged, higher occupancy configs
    tree_conv_smem_kernel<16, 8, 256, 4, true><<<dim3(4, 128), 256, SM_C2>>>(
        (const uint2*)h1, (uint2*)h2, c2i, mixh + OFF_C2 * 4);
    tree_conv_smem_kernel<8, 16, 256, 4, true><<<dim3(2, 512), 256, SM_C3>>>(
        (const uint2*)h2, (uint2*)h3, c3i, mixh + OFF_C3 * 4);
    tree_conv_smem_kernel<4, 32, 128, 8, false><<<dim3(1, 1024), 128, SM_C4>>>(
        (const uint2*)h3, (uint2*)h4, c4i, mixh + OFF_C4 * 4);

    logic_kernel<<<(40960 * 16) / 256, 256>>>((const uint4*)h4, (uint4*)g1, l1a, l1b, (const uint4*)mixh + OFF_L1, 40960);
    logic_kernel<<<(20480 * 16) / 256, 256>>>((const uint4*)g1, (uint4*)g2, l2a, l2b, (const uint4*)mixh + OFF_L2, 20480);
    logic3_sum_kernel<<<160, dim3(32, 4)>>>((const uint2*)g2, (float4*)part, l3a, l3b, mixh + OFF_L3 * 4);
    final_sum_kernel<<<10, 128>>>(part, (float*)d_out);
}